// round 6
// baseline (speedup 1.0000x reference)
#include <cuda_runtime.h>
#include <cuda_fp8.h>
#include <cstdint>
#include <cstddef>

#define DI __device__ __forceinline__

// ---------------- problem constants ----------------
static constexpr int MT = 8192;   // tokens
static constexpr int NT = 4096;   // out features
static constexpr int KT = 4096;   // in features
static constexpr float FP8MAX = 448.0f;
static constexpr float AMAX_EPS = 1e-8f;
static constexpr float MOMENTUM = 0.95f;

// ---------------- GEMM tiling ----------------
static constexpr int BM = 128;
static constexpr int BN = 128;
static constexpr int BK = 128;                 // bytes of e4m3 along K per stage
static constexpr int NSTAGES = 3;
static constexpr int K_ITERS = KT / BK;        // 32
static constexpr int A_BYTES = BM * BK;        // 16384
static constexpr int B_BYTES = BN * BK;        // 16384
static constexpr int STAGE_BYTES = A_BYTES + B_BYTES;          // 32768
static constexpr int DYN_SMEM = NSTAGES * STAGE_BYTES;         // 98304 -> 2 CTAs/SM
static constexpr int THREADS = 256;            // 8 warps: 2 (m) x 4 (n)
static constexpr int GRID = (MT / BM) * (NT / BN);             // 2048

// ---------------- scratch (static device arrays: allocation-guard safe) ----------------
__device__ __align__(128) uint8_t g_Xq[(size_t)MT * KT];
__device__ __align__(128) uint8_t g_Wq[(size_t)NT * KT];
__device__ float g_partX[256];    // 64 m-groups x 4 slices
__device__ float g_partW[32];     // 32 n-groups
__device__ int   g_cntX[64];
__device__ int   g_cntW[32];
__device__ int   g_doneAll;

// ---------------- PTX helpers (base sm_103 target ONLY — no tcgen05/TMA) ----------------
DI uint32_t smem_u32(const void* p) {
    uint32_t a;
    asm("{ .reg .u64 t; cvta.to.shared.u64 t, %1; cvt.u32.u64 %0, t; }" : "=r"(a) : "l"(p));
    return a;
}
DI void cp_async16(uint32_t s, const void* g) {
    asm volatile("cp.async.cg.shared.global [%0], [%1], 16;" :: "r"(s), "l"(g) : "memory");
}
DI void cp_commit() { asm volatile("cp.async.commit_group;" ::: "memory"); }
template <int N> DI void cp_wait() {
    asm volatile("cp.async.wait_group %0;" :: "n"(N) : "memory");
}
DI void ldsm_x4(uint32_t& r0, uint32_t& r1, uint32_t& r2, uint32_t& r3, uint32_t addr) {
    asm volatile("ldmatrix.sync.aligned.m8n8.x4.shared.b16 {%0,%1,%2,%3}, [%4];"
                 : "=r"(r0), "=r"(r1), "=r"(r2), "=r"(r3) : "r"(addr));
}
DI void mma_e4m3(float& c0, float& c1, float& c2, float& c3,
                 uint32_t a0, uint32_t a1, uint32_t a2, uint32_t a3,
                 uint32_t b0, uint32_t b1) {
    asm volatile(
        "mma.sync.aligned.m16n8k32.row.col.f32.e4m3.e4m3.f32 "
        "{%0,%1,%2,%3}, {%4,%5,%6,%7}, {%8,%9}, {%0,%1,%2,%3};"
        : "+f"(c0), "+f"(c1), "+f"(c2), "+f"(c3)
        : "r"(a0), "r"(a1), "r"(a2), "r"(a3), "r"(b0), "r"(b1));
}

// quantize a contiguous float4 range, return thread-local absmax
DI float quant_range(const float4* __restrict__ x4, uint32_t* __restrict__ q4,
                     int base4, int n4, float s, int tid) {
    float lmax = 0.0f;
    for (int i = tid; i < n4; i += THREADS) {
        float4 v = x4[base4 + i];
        lmax = fmaxf(lmax, fmaxf(fmaxf(fabsf(v.x), fabsf(v.y)), fmaxf(fabsf(v.z), fabsf(v.w))));
        uint32_t p =
            (uint32_t)__nv_cvt_float_to_fp8(v.x * s, __NV_SATFINITE, __NV_E4M3)
          | ((uint32_t)__nv_cvt_float_to_fp8(v.y * s, __NV_SATFINITE, __NV_E4M3) << 8)
          | ((uint32_t)__nv_cvt_float_to_fp8(v.z * s, __NV_SATFINITE, __NV_E4M3) << 16)
          | ((uint32_t)__nv_cvt_float_to_fp8(v.w * s, __NV_SATFINITE, __NV_E4M3) << 24);
        q4[base4 + i] = p;
    }
    return lmax;
}

// ---------------- fused kernel: quant + GEMM + amax finalize ----------------
__global__ void __launch_bounds__(THREADS, 2) fused_fp8_linear_kernel(
    const float* __restrict__ x,
    const float* __restrict__ w,
    const float* __restrict__ bias,
    const float* __restrict__ in_amax,
    const float* __restrict__ w_amax,
    float* __restrict__ out, int out_size)
{
    extern __shared__ uint8_t dynsmem[];
    __shared__ float bias_s[BN];
    __shared__ float redbuf[8];
    __shared__ int s_last;

    const int tid  = threadIdx.x;
    const int wid  = tid >> 5;
    const int lane = tid & 31;
    const int wm   = wid >> 2;
    const int wn   = wid & 3;

    const int m_idx = (int)(blockIdx.x >> 5);
    const int n_idx = (int)(blockIdx.x & 31);
    const int m0 = m_idx * BM;
    const int n0 = n_idx * BN;

    for (int i = tid; i < BN; i += THREADS) bias_s[i] = bias[n0 + i];

    // ======== quant phase ========
    // X: blocks with n_idx<4 quant 32 rows of their own m-group (slice n_idx)
    if (n_idx < 4) {
        const float sX = FP8MAX / fmaxf(in_amax[0], AMAX_EPS);
        const int base4 = (m0 + n_idx * 32) * (KT / 4);
        float lm = quant_range((const float4*)x, (uint32_t*)g_Xq, base4, 32 * (KT / 4), sX, tid);
        #pragma unroll
        for (int o = 16; o > 0; o >>= 1) lm = fmaxf(lm, __shfl_xor_sync(0xffffffffu, lm, o));
        if (lane == 0) redbuf[wid] = lm;
        __syncthreads();
        if (tid == 0) {
            float b = redbuf[0];
            #pragma unroll
            for (int ww = 1; ww < 8; ++ww) b = fmaxf(b, redbuf[ww]);
            g_partX[m_idx * 4 + n_idx] = b;
        }
        __threadfence();
        __syncthreads();
        if (tid == 0) atomicAdd(&g_cntX[m_idx], 1);
    }
    // W: block (0, n) quants the whole W group n (128 rows)
    if (m_idx == 0) {
        const float sW = FP8MAX / fmaxf(w_amax[0], AMAX_EPS);
        const int base4 = n0 * (KT / 4);
        float lm = quant_range((const float4*)w, (uint32_t*)g_Wq, base4, BN * (KT / 4), sW, tid);
        #pragma unroll
        for (int o = 16; o > 0; o >>= 1) lm = fmaxf(lm, __shfl_xor_sync(0xffffffffu, lm, o));
        __syncthreads();   // protect redbuf reuse
        if (lane == 0) redbuf[wid] = lm;
        __syncthreads();
        if (tid == 0) {
            float b = redbuf[0];
            #pragma unroll
            for (int ww = 1; ww < 8; ++ww) b = fmaxf(b, redbuf[ww]);
            g_partW[n_idx] = b;
        }
        __threadfence();
        __syncthreads();
        if (tid == 0) atomicAdd(&g_cntW[n_idx], 1);
    }

    // ======== wait for operand tiles ========
    if (tid == 0) {
        volatile int* cX = g_cntX + m_idx;
        volatile int* cW = g_cntW + n_idx;
        while (*cX < 4) __nanosleep(64);
        while (*cW < 1) __nanosleep(64);
    }
    __syncthreads();

    // ======== GEMM ========
    const uint32_t smem = smem_u32(dynsmem);
    const uint8_t* Ag = g_Xq + (size_t)m0 * KT;
    const uint8_t* Bg = g_Wq + (size_t)n0 * KT;

    // ---- prologue ----
    #pragma unroll
    for (int s = 0; s < NSTAGES - 1; ++s) {
        const uint32_t a_s = smem + s * STAGE_BYTES;
        const uint32_t b_s = a_s + A_BYTES;
        const int kb = s * BK;
        #pragma unroll
        for (int i = 0; i < 8; ++i) {
            const int q = tid + i * THREADS;
            if (q < 1024) {
                const int row = q >> 3, ch = (q & 7) << 4;
                const uint32_t o = (uint32_t)(row * BK + ch);
                cp_async16(a_s + (o ^ ((o >> 3) & 0x70)), Ag + (size_t)row * KT + kb + ch);
            } else {
                const int qb = q - 1024;
                const int row = qb >> 3, ch = (qb & 7) << 4;
                const uint32_t o = (uint32_t)(row * BK + ch);
                cp_async16(b_s + (o ^ ((o >> 3) & 0x70)), Bg + (size_t)row * KT + kb + ch);
            }
        }
        cp_commit();
    }

    // ---- per-lane ldmatrix offsets ----
    const int a_row_l = (lane & 15);
    const uint32_t a_kchunk = (uint32_t)((lane >> 4) << 4);
    const int b_row_l = ((lane >> 4) << 3) + (lane & 7);
    const uint32_t b_kchunk = (uint32_t)(((lane >> 3) & 1) << 4);

    uint32_t a_base[4], b_base[2];
    uint32_t a_xor, b_xor;
    {
        #pragma unroll
        for (int am = 0; am < 4; ++am) {
            const int r = wm * 64 + am * 16 + a_row_l;
            a_base[am] = (uint32_t)(r * BK);
        }
        a_xor = (uint32_t)(((wm * 64 + a_row_l) & 7) << 4);
        #pragma unroll
        for (int bp = 0; bp < 2; ++bp) {
            const int r = wn * 32 + bp * 16 + b_row_l;
            b_base[bp] = (uint32_t)(r * BK);
        }
        b_xor = (uint32_t)(((wn * 32 + b_row_l) & 7) << 4);
    }

    float acc[4][4][4];
    #pragma unroll
    for (int i = 0; i < 4; ++i)
        #pragma unroll
        for (int j = 0; j < 4; ++j)
            #pragma unroll
            for (int k = 0; k < 4; ++k) acc[i][j][k] = 0.0f;

    // ---- main loop ----
    for (int it = 0; it < K_ITERS; ++it) {
        cp_wait<NSTAGES - 2>();
        __syncthreads();

        const int nit = it + NSTAGES - 1;
        if (nit < K_ITERS) {
            const int st = nit % NSTAGES;
            const uint32_t a_s = smem + st * STAGE_BYTES;
            const uint32_t b_s = a_s + A_BYTES;
            const int kb = nit * BK;
            #pragma unroll
            for (int i = 0; i < 8; ++i) {
                const int q = tid + i * THREADS;
                if (q < 1024) {
                    const int row = q >> 3, ch = (q & 7) << 4;
                    const uint32_t o = (uint32_t)(row * BK + ch);
                    cp_async16(a_s + (o ^ ((o >> 3) & 0x70)), Ag + (size_t)row * KT + kb + ch);
                } else {
                    const int qb = q - 1024;
                    const int row = qb >> 3, ch = (qb & 7) << 4;
                    const uint32_t o = (uint32_t)(row * BK + ch);
                    cp_async16(b_s + (o ^ ((o >> 3) & 0x70)), Bg + (size_t)row * KT + kb + ch);
                }
            }
        }
        cp_commit();

        const uint32_t a_s = smem + (it % NSTAGES) * STAGE_BYTES;
        const uint32_t b_s = a_s + A_BYTES;

        #pragma unroll
        for (int ka = 0; ka < BK / 32; ++ka) {
            const uint32_t koffA = ((uint32_t)(ka * 32) + a_kchunk) ^ a_xor;
            const uint32_t koffB = ((uint32_t)(ka * 32) + b_kchunk) ^ b_xor;
            uint32_t af[4][4];
            #pragma unroll
            for (int am = 0; am < 4; ++am)
                ldsm_x4(af[am][0], af[am][1], af[am][2], af[am][3],
                        a_s + a_base[am] + koffA);
            uint32_t bf[2][4];
            #pragma unroll
            for (int bp = 0; bp < 2; ++bp)
                ldsm_x4(bf[bp][0], bf[bp][1], bf[bp][2], bf[bp][3],
                        b_s + b_base[bp] + koffB);
            #pragma unroll
            for (int am = 0; am < 4; ++am) {
                #pragma unroll
                for (int an = 0; an < 4; ++an) {
                    const int bp = an >> 1;
                    const int hl = (an & 1) << 1;
                    mma_e4m3(acc[am][an][0], acc[am][an][1], acc[am][an][2], acc[am][an][3],
                             af[am][0], af[am][1], af[am][2], af[am][3],
                             bf[bp][hl + 0], bf[bp][hl + 1]);
                }
            }
        }
    }

    // ---- epilogue: scale + bias + store ----
    const float sx = FP8MAX / fmaxf(in_amax[0], AMAX_EPS);
    const float sw = FP8MAX / fmaxf(w_amax[0], AMAX_EPS);
    const float inv = 1.0f / (sx * sw);

    const int row_base = m0 + wm * 64 + (lane >> 2);
    const int col_base = n0 + wn * 32 + (lane & 3) * 2;
    #pragma unroll
    for (int am = 0; am < 4; ++am) {
        #pragma unroll
        for (int an = 0; an < 4; ++an) {
            const int c = col_base + an * 8;
            const float b0 = bias_s[c - n0], b1 = bias_s[c - n0 + 1];
            const int r0 = row_base + am * 16;
            float2 v0 = make_float2(fmaf(acc[am][an][0], inv, b0),
                                    fmaf(acc[am][an][1], inv, b1));
            float2 v1 = make_float2(fmaf(acc[am][an][2], inv, b0),
                                    fmaf(acc[am][an][3], inv, b1));
            *(float2*)(out + (size_t)r0 * NT + c) = v0;
            *(float2*)(out + (size_t)(r0 + 8) * NT + c) = v1;
        }
    }

    // ======== done counter + amax finalize + reset (last block) ========
    __syncthreads();
    if (tid == 0) s_last = (atomicAdd(&g_doneAll, 1) == GRID - 1) ? 1 : 0;
    __syncthreads();
    if (s_last && wid == 0) {
        float mx = 0.0f, mw = 0.0f;
        for (int i = lane; i < 256; i += 32) mx = fmaxf(mx, g_partX[i]);
        if (lane < 32) mw = fmaxf(mw, g_partW[lane]);
        #pragma unroll
        for (int o = 16; o > 0; o >>= 1) {
            mx = fmaxf(mx, __shfl_xor_sync(0xffffffffu, mx, o));
            mw = fmaxf(mw, __shfl_xor_sync(0xffffffffu, mw, o));
        }
        if (lane == 0) {
            out[out_size - 2] = fmaxf(fmaxf(in_amax[0] * MOMENTUM, mx), AMAX_EPS);
            out[out_size - 1] = fmaxf(fmaxf(w_amax[0] * MOMENTUM, mw), AMAX_EPS);
        }
        // reset counters for next (graph-replayed) launch
        for (int i = lane; i < 64; i += 32) g_cntX[i] = 0;
        g_cntW[lane] = 0;
        if (lane == 0) g_doneAll = 0;
        __threadfence();
    }
}

// ---------------- launch: ONE kernel ----------------
extern "C" void kernel_launch(void* const* d_in, const int* in_sizes, int n_in,
                              void* d_out, int out_size) {
    (void)in_sizes; (void)n_in;
    const float* x       = (const float*)d_in[0];
    const float* w       = (const float*)d_in[1];
    const float* bias    = (const float*)d_in[2];
    const float* in_amax = (const float*)d_in[3];
    const float* w_amax  = (const float*)d_in[4];
    float* out = (float*)d_out;

    cudaFuncSetAttribute(fused_fp8_linear_kernel,
                         cudaFuncAttributeMaxDynamicSharedMemorySize, DYN_SMEM);
    fused_fp8_linear_kernel<<<GRID, THREADS, DYN_SMEM>>>(
        x, w, bias, in_amax, w_amax, out, out_size);
}

// round 7
// speedup vs baseline: 1.8176x; 1.8176x over previous
#include <cuda_runtime.h>
#include <cuda_fp8.h>
#include <cstdint>
#include <cstddef>

#define DI __device__ __forceinline__

// ---------------- problem constants ----------------
static constexpr int MT = 8192;   // tokens
static constexpr int NT = 4096;   // out features
static constexpr int KT = 4096;   // in features
static constexpr float FP8MAX = 448.0f;
static constexpr float AMAX_EPS = 1e-8f;
static constexpr float MOMENTUM = 0.95f;

// ---------------- GEMM tiling ----------------
static constexpr int BM = 128;
static constexpr int BN = 256;
static constexpr int BK = 128;                 // e4m3 bytes along K per stage
static constexpr int NSTAGES = 4;
static constexpr int K_ITERS = KT / BK;        // 32
static constexpr int A_BYTES = BM * BK;        // 16384
static constexpr int B_BYTES = BN * BK;        // 32768
static constexpr int STAGE_BYTES = A_BYTES + B_BYTES;   // 49152
static constexpr int DYN_SMEM = NSTAGES * STAGE_BYTES;  // 196608
static constexpr int THREADS = 256;            // 8 warps: 2(m) x 4(n), warp tile 64x64
static constexpr int CHUNKS = STAGE_BYTES / 16;         // 3072 (12/thread)

static constexpr int QX_BLOCKS = 1024;
static constexpr int QW_BLOCKS = 512;

// ---------------- scratch ----------------
__device__ __align__(128) uint8_t g_Xq[(size_t)MT * KT];
__device__ __align__(128) uint8_t g_Wq[(size_t)NT * KT];
__device__ float g_partX[QX_BLOCKS];
__device__ float g_partW[QW_BLOCKS];

// ---------------- PTX helpers (base sm_103 target ONLY) ----------------
DI uint32_t smem_u32(const void* p) {
    uint32_t a;
    asm("{ .reg .u64 t; cvta.to.shared.u64 t, %1; cvt.u32.u64 %0, t; }" : "=r"(a) : "l"(p));
    return a;
}
DI void cp_async16(uint32_t s, const void* g) {
    asm volatile("cp.async.cg.shared.global [%0], [%1], 16;" :: "r"(s), "l"(g) : "memory");
}
DI void cp_commit() { asm volatile("cp.async.commit_group;" ::: "memory"); }
template <int N> DI void cp_wait() {
    asm volatile("cp.async.wait_group %0;" :: "n"(N) : "memory");
}
DI void ldsm_x4(uint32_t& r0, uint32_t& r1, uint32_t& r2, uint32_t& r3, uint32_t addr) {
    asm volatile("ldmatrix.sync.aligned.m8n8.x4.shared.b16 {%0,%1,%2,%3}, [%4];"
                 : "=r"(r0), "=r"(r1), "=r"(r2), "=r"(r3) : "r"(addr));
}
DI void mma_e4m3(float& c0, float& c1, float& c2, float& c3,
                 uint32_t a0, uint32_t a1, uint32_t a2, uint32_t a3,
                 uint32_t b0, uint32_t b1) {
    asm volatile(
        "mma.sync.aligned.m16n8k32.row.col.f32.e4m3.e4m3.f32 "
        "{%0,%1,%2,%3}, {%4,%5,%6,%7}, {%8,%9}, {%0,%1,%2,%3};"
        : "+f"(c0), "+f"(c1), "+f"(c2), "+f"(c3)
        : "r"(a0), "r"(a1), "r"(a2), "r"(a3), "r"(b0), "r"(b1));
}

// ---------------- kernel 1: quantize + per-block absmax ----------------
__global__ void quant_amax_kernel(const float* __restrict__ x, uint8_t* __restrict__ q,
                                  int n4, const float* __restrict__ amax_in,
                                  float* __restrict__ part) {
    __shared__ float smax[8];
    const float s = FP8MAX / fmaxf(amax_in[0], AMAX_EPS);
    float lmax = 0.0f;
    const float4* x4 = (const float4*)x;
    uint32_t* q4 = (uint32_t*)q;
    for (int i = blockIdx.x * blockDim.x + threadIdx.x; i < n4; i += gridDim.x * blockDim.x) {
        float4 v = x4[i];
        lmax = fmaxf(lmax, fmaxf(fmaxf(fabsf(v.x), fabsf(v.y)), fmaxf(fabsf(v.z), fabsf(v.w))));
        uint32_t p =
            (uint32_t)__nv_cvt_float_to_fp8(v.x * s, __NV_SATFINITE, __NV_E4M3)
          | ((uint32_t)__nv_cvt_float_to_fp8(v.y * s, __NV_SATFINITE, __NV_E4M3) << 8)
          | ((uint32_t)__nv_cvt_float_to_fp8(v.z * s, __NV_SATFINITE, __NV_E4M3) << 16)
          | ((uint32_t)__nv_cvt_float_to_fp8(v.w * s, __NV_SATFINITE, __NV_E4M3) << 24);
        q4[i] = p;
    }
    #pragma unroll
    for (int o = 16; o > 0; o >>= 1) lmax = fmaxf(lmax, __shfl_xor_sync(0xffffffffu, lmax, o));
    if ((threadIdx.x & 31) == 0) smax[threadIdx.x >> 5] = lmax;
    __syncthreads();
    if (threadIdx.x == 0) {
        float b = smax[0];
        for (int w = 1; w < (int)(blockDim.x >> 5); ++w) b = fmaxf(b, smax[w]);
        part[blockIdx.x] = b;
    }
}

// ---------------- kernel 2: fp8 GEMM (warp tile 64x64) + bias + fused amax ----------------
__global__ void __launch_bounds__(THREADS, 1) fp8_gemm_kernel(
    const float* __restrict__ bias,
    const float* __restrict__ in_amax,
    const float* __restrict__ w_amax,
    const float* __restrict__ partX,
    const float* __restrict__ partW,
    float* __restrict__ out, int out_size)
{
    extern __shared__ uint8_t dynsmem[];
    __shared__ float bias_s[BN];

    const int tid  = threadIdx.x;
    const int wid  = tid >> 5;
    const int lane = tid & 31;
    const int wm   = wid >> 2;        // 0..1, 64 rows each
    const int wn   = wid & 3;         // 0..3, 64 cols each

    const int n_tiles = NT / BN;                  // 16
    const int m0 = (int)(blockIdx.x >> 4) * BM;   // n-fast rasterization
    const int n0 = (int)(blockIdx.x & (n_tiles - 1)) * BN;

    const uint32_t smem = smem_u32(dynsmem);
    const uint8_t* Ag = g_Xq + (size_t)m0 * KT;
    const uint8_t* Bg = g_Wq + (size_t)n0 * KT;

    for (int i = tid; i < BN; i += THREADS) bias_s[i] = bias[n0 + i];

    // ---- prologue: stages 0..NSTAGES-2 ----
    #pragma unroll
    for (int s = 0; s < NSTAGES - 1; ++s) {
        const uint32_t a_s = smem + s * STAGE_BYTES;
        const uint32_t b_s = a_s + A_BYTES;
        const int kb = s * BK;
        #pragma unroll
        for (int i = 0; i < CHUNKS / THREADS; ++i) {
            const int q = tid + i * THREADS;
            if (q < 1024) {                      // A: 128 rows x 8 chunks
                const int row = q >> 3, ch = (q & 7) << 4;
                const uint32_t o = (uint32_t)(row * BK + ch);
                cp_async16(a_s + (o ^ ((o >> 3) & 0x70)), Ag + (size_t)row * KT + kb + ch);
            } else {                             // B: 256 rows x 8 chunks
                const int qb = q - 1024;
                const int row = qb >> 3, ch = (qb & 7) << 4;
                const uint32_t o = (uint32_t)(row * BK + ch);
                cp_async16(b_s + (o ^ ((o >> 3) & 0x70)), Bg + (size_t)row * KT + kb + ch);
            }
        }
        cp_commit();
    }

    // ---- per-lane ldmatrix offsets ----
    const int a_row_l = (lane & 15);
    const uint32_t a_kchunk = (uint32_t)((lane >> 4) << 4);
    const int b_row_l = ((lane >> 4) << 3) + (lane & 7);
    const uint32_t b_kchunk = (uint32_t)(((lane >> 3) & 1) << 4);

    uint32_t a_base[4], b_base[4];
    uint32_t a_xor, b_xor;
    {
        #pragma unroll
        for (int am = 0; am < 4; ++am) {
            const int r = wm * 64 + am * 16 + a_row_l;
            a_base[am] = (uint32_t)(r * BK);
        }
        a_xor = (uint32_t)(((wm * 64 + a_row_l) & 7) << 4);
        #pragma unroll
        for (int bp = 0; bp < 4; ++bp) {
            const int r = wn * 64 + bp * 16 + b_row_l;
            b_base[bp] = (uint32_t)(r * BK);
        }
        b_xor = (uint32_t)(((wn * 64 + b_row_l) & 7) << 4);
    }

    float acc[4][8][4];
    #pragma unroll
    for (int i = 0; i < 4; ++i)
        #pragma unroll
        for (int j = 0; j < 8; ++j)
            #pragma unroll
            for (int k = 0; k < 4; ++k) acc[i][j][k] = 0.0f;

    // ---- main loop ----
    for (int it = 0; it < K_ITERS; ++it) {
        cp_wait<NSTAGES - 2>();
        __syncthreads();

        const int nit = it + NSTAGES - 1;
        if (nit < K_ITERS) {
            const int st = nit & (NSTAGES - 1);
            const uint32_t a_s = smem + st * STAGE_BYTES;
            const uint32_t b_s = a_s + A_BYTES;
            const int kb = nit * BK;
            #pragma unroll
            for (int i = 0; i < CHUNKS / THREADS; ++i) {
                const int q = tid + i * THREADS;
                if (q < 1024) {
                    const int row = q >> 3, ch = (q & 7) << 4;
                    const uint32_t o = (uint32_t)(row * BK + ch);
                    cp_async16(a_s + (o ^ ((o >> 3) & 0x70)), Ag + (size_t)row * KT + kb + ch);
                } else {
                    const int qb = q - 1024;
                    const int row = qb >> 3, ch = (qb & 7) << 4;
                    const uint32_t o = (uint32_t)(row * BK + ch);
                    cp_async16(b_s + (o ^ ((o >> 3) & 0x70)), Bg + (size_t)row * KT + kb + ch);
                }
            }
        }
        cp_commit();

        const uint32_t a_s = smem + (it & (NSTAGES - 1)) * STAGE_BYTES;
        const uint32_t b_s = a_s + A_BYTES;

        #pragma unroll
        for (int ka = 0; ka < BK / 32; ++ka) {
            const uint32_t koffA = ((uint32_t)(ka * 32) + a_kchunk) ^ a_xor;
            const uint32_t koffB = ((uint32_t)(ka * 32) + b_kchunk) ^ b_xor;
            uint32_t af[4][4];
            #pragma unroll
            for (int am = 0; am < 4; ++am)
                ldsm_x4(af[am][0], af[am][1], af[am][2], af[am][3],
                        a_s + a_base[am] + koffA);
            uint32_t bf[4][4];
            #pragma unroll
            for (int bp = 0; bp < 4; ++bp)
                ldsm_x4(bf[bp][0], bf[bp][1], bf[bp][2], bf[bp][3],
                        b_s + b_base[bp] + koffB);
            #pragma unroll
            for (int am = 0; am < 4; ++am) {
                #pragma unroll
                for (int an = 0; an < 8; ++an) {
                    const int bp = an >> 1;
                    const int hl = (an & 1) << 1;
                    mma_e4m3(acc[am][an][0], acc[am][an][1], acc[am][an][2], acc[am][an][3],
                             af[am][0], af[am][1], af[am][2], af[am][3],
                             bf[bp][hl + 0], bf[bp][hl + 1]);
                }
            }
        }
    }

    // ---- epilogue ----
    const float sx = FP8MAX / fmaxf(in_amax[0], AMAX_EPS);
    const float sw = FP8MAX / fmaxf(w_amax[0], AMAX_EPS);
    const float inv = 1.0f / (sx * sw);

    const int row_base = m0 + wm * 64 + (lane >> 2);
    const int col_base = n0 + wn * 64 + (lane & 3) * 2;
    #pragma unroll
    for (int am = 0; am < 4; ++am) {
        #pragma unroll
        for (int an = 0; an < 8; ++an) {
            const int c = col_base + an * 8;
            const float b0 = bias_s[c - n0], b1 = bias_s[c - n0 + 1];
            const int r0 = row_base + am * 16;
            float2 v0 = make_float2(fmaf(acc[am][an][0], inv, b0),
                                    fmaf(acc[am][an][1], inv, b1));
            float2 v1 = make_float2(fmaf(acc[am][an][2], inv, b0),
                                    fmaf(acc[am][an][3], inv, b1));
            *(float2*)(out + (size_t)r0 * NT + c) = v0;
            *(float2*)(out + (size_t)(r0 + 8) * NT + c) = v1;
        }
    }

    // ---- fused amax EMA finalize (block 0, warp 0) ----
    if (blockIdx.x == 0 && wid == 0) {
        float mx = 0.0f, mw = 0.0f;
        for (int i = lane; i < QX_BLOCKS; i += 32) mx = fmaxf(mx, partX[i]);
        for (int i = lane; i < QW_BLOCKS; i += 32) mw = fmaxf(mw, partW[i]);
        #pragma unroll
        for (int o = 16; o > 0; o >>= 1) {
            mx = fmaxf(mx, __shfl_xor_sync(0xffffffffu, mx, o));
            mw = fmaxf(mw, __shfl_xor_sync(0xffffffffu, mw, o));
        }
        if (lane == 0) {
            out[out_size - 2] = fmaxf(fmaxf(in_amax[0] * MOMENTUM, mx), AMAX_EPS);
            out[out_size - 1] = fmaxf(fmaxf(w_amax[0] * MOMENTUM, mw), AMAX_EPS);
        }
    }
}

// ---------------- launch: 3 kernels ----------------
extern "C" void kernel_launch(void* const* d_in, const int* in_sizes, int n_in,
                              void* d_out, int out_size) {
    (void)in_sizes; (void)n_in;
    const float* x       = (const float*)d_in[0];
    const float* w       = (const float*)d_in[1];
    const float* bias    = (const float*)d_in[2];
    const float* in_amax = (const float*)d_in[3];
    const float* w_amax  = (const float*)d_in[4];
    float* out = (float*)d_out;

    void* p;
    cudaGetSymbolAddress(&p, g_Xq);    uint8_t* xq = (uint8_t*)p;
    cudaGetSymbolAddress(&p, g_Wq);    uint8_t* wq = (uint8_t*)p;
    cudaGetSymbolAddress(&p, g_partX); float* partX = (float*)p;
    cudaGetSymbolAddress(&p, g_partW); float* partW = (float*)p;

    quant_amax_kernel<<<QX_BLOCKS, 256>>>(x, xq, MT * KT / 4, in_amax, partX);
    quant_amax_kernel<<<QW_BLOCKS, 256>>>(w, wq, NT * KT / 4, w_amax, partW);

    cudaFuncSetAttribute(fp8_gemm_kernel,
                         cudaFuncAttributeMaxDynamicSharedMemorySize, DYN_SMEM);
    fp8_gemm_kernel<<<(MT / BM) * (NT / BN), THREADS, DYN_SMEM>>>(
        bias, in_amax, w_amax, partX, partW, out, out_size);
}

// round 8
// speedup vs baseline: 1.9217x; 1.0573x over previous
#include <cuda_runtime.h>
#include <cuda_fp8.h>
#include <cstdint>
#include <cstddef>

#define DI __device__ __forceinline__

// ---------------- problem constants ----------------
static constexpr int MT = 8192;   // tokens
static constexpr int NT = 4096;   // out features
static constexpr int KT = 4096;   // in features
static constexpr float FP8MAX = 448.0f;
static constexpr float AMAX_EPS = 1e-8f;
static constexpr float MOMENTUM = 0.95f;

// ---------------- GEMM tiling (R5 proven config) ----------------
static constexpr int BM = 128;
static constexpr int BN = 128;
static constexpr int BK = 128;                 // e4m3 bytes along K per stage
static constexpr int NSTAGES = 3;
static constexpr int K_ITERS = KT / BK;        // 32
static constexpr int A_BYTES = BM * BK;        // 16384
static constexpr int B_BYTES = BN * BK;        // 16384
static constexpr int STAGE_BYTES = A_BYTES + B_BYTES;   // 32768
static constexpr int DYN_SMEM = NSTAGES * STAGE_BYTES;  // 98304 -> 2 CTAs/SM
static constexpr int THREADS = 256;            // 8 warps: 2(m) x 4(n), warp 64x32

// quant grid split
static constexpr int QX_BLOCKS = 1024;
static constexpr int QW_BLOCKS = 512;
static constexpr int Q_BLOCKS  = QX_BLOCKS + QW_BLOCKS;   // 1536

// ---------------- scratch ----------------
__device__ __align__(128) uint8_t g_Xq[(size_t)MT * KT];
__device__ __align__(128) uint8_t g_Wq[(size_t)NT * KT];
__device__ float g_partX[QX_BLOCKS];
__device__ float g_partW[QW_BLOCKS];

// ---------------- PTX helpers (base sm_103 target ONLY) ----------------
DI uint32_t smem_u32(const void* p) {
    uint32_t a;
    asm("{ .reg .u64 t; cvta.to.shared.u64 t, %1; cvt.u32.u64 %0, t; }" : "=r"(a) : "l"(p));
    return a;
}
DI void cp_async16(uint32_t s, const void* g) {
    asm volatile("cp.async.cg.shared.global [%0], [%1], 16;" :: "r"(s), "l"(g) : "memory");
}
DI void cp_commit() { asm volatile("cp.async.commit_group;" ::: "memory"); }
template <int N> DI void cp_wait() {
    asm volatile("cp.async.wait_group %0;" :: "n"(N) : "memory");
}
DI void ldsm_x4(uint32_t& r0, uint32_t& r1, uint32_t& r2, uint32_t& r3, uint32_t addr) {
    asm volatile("ldmatrix.sync.aligned.m8n8.x4.shared.b16 {%0,%1,%2,%3}, [%4];"
                 : "=r"(r0), "=r"(r1), "=r"(r2), "=r"(r3) : "r"(addr));
}
DI void mma_e4m3(float& c0, float& c1, float& c2, float& c3,
                 uint32_t a0, uint32_t a1, uint32_t a2, uint32_t a3,
                 uint32_t b0, uint32_t b1) {
    asm volatile(
        "mma.sync.aligned.m16n8k32.row.col.f32.e4m3.e4m3.f32 "
        "{%0,%1,%2,%3}, {%4,%5,%6,%7}, {%8,%9}, {%0,%1,%2,%3};"
        : "+f"(c0), "+f"(c1), "+f"(c2), "+f"(c3)
        : "r"(a0), "r"(a1), "r"(a2), "r"(a3), "r"(b0), "r"(b1));
}
// pack two scaled floats into e4m3x2 (lo = first arg)
DI uint32_t cvt_e4m3x2(float lo, float hi) {
    uint16_t r;
    asm("cvt.rn.satfinite.e4m3x2.f32 %0, %1, %2;" : "=h"(r) : "f"(hi), "f"(lo));
    return (uint32_t)r;
}

// ---------------- kernel 1: combined quantize X + W, per-block absmax ----------------
__global__ void quant_amax_kernel(const float* __restrict__ x,
                                  const float* __restrict__ w,
                                  const float* __restrict__ in_amax,
                                  const float* __restrict__ w_amax) {
    __shared__ float smax[8];
    const bool isX = (blockIdx.x < QX_BLOCKS);
    const int bid  = isX ? (int)blockIdx.x : (int)blockIdx.x - QX_BLOCKS;
    const int nblk = isX ? QX_BLOCKS : QW_BLOCKS;
    const int n4   = isX ? MT * KT / 4 : NT * KT / 4;
    const float4* src4 = (const float4*)(isX ? x : w);
    uint32_t* dst4 = (uint32_t*)(isX ? g_Xq : g_Wq);
    const float s = FP8MAX / fmaxf((isX ? in_amax : w_amax)[0], AMAX_EPS);

    float lmax = 0.0f;
    for (int i = bid * blockDim.x + threadIdx.x; i < n4; i += nblk * blockDim.x) {
        float4 v = src4[i];
        lmax = fmaxf(lmax, fmaxf(fmaxf(fabsf(v.x), fabsf(v.y)), fmaxf(fabsf(v.z), fabsf(v.w))));
        const uint32_t lo = cvt_e4m3x2(v.x * s, v.y * s);
        const uint32_t hi = cvt_e4m3x2(v.z * s, v.w * s);
        dst4[i] = lo | (hi << 16);
    }
    #pragma unroll
    for (int o = 16; o > 0; o >>= 1) lmax = fmaxf(lmax, __shfl_xor_sync(0xffffffffu, lmax, o));
    if ((threadIdx.x & 31) == 0) smax[threadIdx.x >> 5] = lmax;
    __syncthreads();
    if (threadIdx.x == 0) {
        float b = smax[0];
        #pragma unroll
        for (int ww = 1; ww < 8; ++ww) b = fmaxf(b, smax[ww]);
        (isX ? g_partX : g_partW)[bid] = b;
    }
}

// ---------------- kernel 2: fp8 mma.sync GEMM + bias + fused amax finalize ----------------
__global__ void __launch_bounds__(THREADS, 2) fp8_gemm_kernel(
    const float* __restrict__ bias,
    const float* __restrict__ in_amax,
    const float* __restrict__ w_amax,
    float* __restrict__ out, int out_size)
{
    extern __shared__ uint8_t dynsmem[];
    __shared__ float bias_s[BN];

    const int tid  = threadIdx.x;
    const int wid  = tid >> 5;
    const int lane = tid & 31;
    const int wm   = wid >> 2;        // 0..1  (64 rows each)
    const int wn   = wid & 3;         // 0..3  (32 cols each)

    const int n_tiles = NT / BN;                       // 32
    const int m0 = (int)(blockIdx.x >> 5) * BM;        // n-fast rasterization
    const int n0 = (int)(blockIdx.x & (n_tiles - 1)) * BN;

    const uint32_t smem = smem_u32(dynsmem);
    const uint8_t* Ag = g_Xq + (size_t)m0 * KT;
    const uint8_t* Bg = g_Wq + (size_t)n0 * KT;

    for (int i = tid; i < BN; i += THREADS) bias_s[i] = bias[n0 + i];

    // ---- prologue: stages 0..NSTAGES-2 ----
    #pragma unroll
    for (int s = 0; s < NSTAGES - 1; ++s) {
        const uint32_t a_s = smem + s * STAGE_BYTES;
        const uint32_t b_s = a_s + A_BYTES;
        const int kb = s * BK;
        #pragma unroll
        for (int i = 0; i < 8; ++i) {
            const int q = tid + i * THREADS;
            if (q < 1024) {
                const int row = q >> 3, ch = (q & 7) << 4;
                const uint32_t o = (uint32_t)(row * BK + ch);
                cp_async16(a_s + (o ^ ((o >> 3) & 0x70)), Ag + (size_t)row * KT + kb + ch);
            } else {
                const int qb = q - 1024;
                const int row = qb >> 3, ch = (qb & 7) << 4;
                const uint32_t o = (uint32_t)(row * BK + ch);
                cp_async16(b_s + (o ^ ((o >> 3) & 0x70)), Bg + (size_t)row * KT + kb + ch);
            }
        }
        cp_commit();
    }

    // ---- per-lane ldmatrix offsets ----
    const int a_row_l = (lane & 15);
    const uint32_t a_kchunk = (uint32_t)((lane >> 4) << 4);
    const int b_row_l = ((lane >> 4) << 3) + (lane & 7);
    const uint32_t b_kchunk = (uint32_t)(((lane >> 3) & 1) << 4);

    uint32_t a_base[4], b_base[2];
    uint32_t a_xor, b_xor;
    {
        #pragma unroll
        for (int am = 0; am < 4; ++am) {
            const int r = wm * 64 + am * 16 + a_row_l;
            a_base[am] = (uint32_t)(r * BK);
        }
        a_xor = (uint32_t)(((wm * 64 + a_row_l) & 7) << 4);
        #pragma unroll
        for (int bp = 0; bp < 2; ++bp) {
            const int r = wn * 32 + bp * 16 + b_row_l;
            b_base[bp] = (uint32_t)(r * BK);
        }
        b_xor = (uint32_t)(((wn * 32 + b_row_l) & 7) << 4);
    }

    float acc[4][4][4];
    #pragma unroll
    for (int i = 0; i < 4; ++i)
        #pragma unroll
        for (int j = 0; j < 4; ++j)
            #pragma unroll
            for (int k = 0; k < 4; ++k) acc[i][j][k] = 0.0f;

    // ---- main loop ----
    for (int it = 0; it < K_ITERS; ++it) {
        cp_wait<NSTAGES - 2>();
        __syncthreads();

        const int nit = it + NSTAGES - 1;
        if (nit < K_ITERS) {
            const int st = nit % NSTAGES;
            const uint32_t a_s = smem + st * STAGE_BYTES;
            const uint32_t b_s = a_s + A_BYTES;
            const int kb = nit * BK;
            #pragma unroll
            for (int i = 0; i < 8; ++i) {
                const int q = tid + i * THREADS;
                if (q < 1024) {
                    const int row = q >> 3, ch = (q & 7) << 4;
                    const uint32_t o = (uint32_t)(row * BK + ch);
                    cp_async16(a_s + (o ^ ((o >> 3) & 0x70)), Ag + (size_t)row * KT + kb + ch);
                } else {
                    const int qb = q - 1024;
                    const int row = qb >> 3, ch = (qb & 7) << 4;
                    const uint32_t o = (uint32_t)(row * BK + ch);
                    cp_async16(b_s + (o ^ ((o >> 3) & 0x70)), Bg + (size_t)row * KT + kb + ch);
                }
            }
        }
        cp_commit();

        const uint32_t a_s = smem + (it % NSTAGES) * STAGE_BYTES;
        const uint32_t b_s = a_s + A_BYTES;

        #pragma unroll
        for (int ka = 0; ka < BK / 32; ++ka) {
            const uint32_t koffA = ((uint32_t)(ka * 32) + a_kchunk) ^ a_xor;
            const uint32_t koffB = ((uint32_t)(ka * 32) + b_kchunk) ^ b_xor;
            uint32_t af[4][4];
            #pragma unroll
            for (int am = 0; am < 4; ++am)
                ldsm_x4(af[am][0], af[am][1], af[am][2], af[am][3],
                        a_s + a_base[am] + koffA);
            uint32_t bf[2][4];
            #pragma unroll
            for (int bp = 0; bp < 2; ++bp)
                ldsm_x4(bf[bp][0], bf[bp][1], bf[bp][2], bf[bp][3],
                        b_s + b_base[bp] + koffB);
            #pragma unroll
            for (int am = 0; am < 4; ++am) {
                #pragma unroll
                for (int an = 0; an < 4; ++an) {
                    const int bp = an >> 1;
                    const int hl = (an & 1) << 1;
                    mma_e4m3(acc[am][an][0], acc[am][an][1], acc[am][an][2], acc[am][an][3],
                             af[am][0], af[am][1], af[am][2], af[am][3],
                             bf[bp][hl + 0], bf[bp][hl + 1]);
                }
            }
        }
    }

    // ---- epilogue: scale + bias + store ----
    const float sx = FP8MAX / fmaxf(in_amax[0], AMAX_EPS);
    const float sw = FP8MAX / fmaxf(w_amax[0], AMAX_EPS);
    const float inv = 1.0f / (sx * sw);

    const int row_base = m0 + wm * 64 + (lane >> 2);
    const int col_base = n0 + wn * 32 + (lane & 3) * 2;
    #pragma unroll
    for (int am = 0; am < 4; ++am) {
        #pragma unroll
        for (int an = 0; an < 4; ++an) {
            const int c = col_base + an * 8;
            const float b0 = bias_s[c - n0], b1 = bias_s[c - n0 + 1];
            const int r0 = row_base + am * 16;
            float2 v0 = make_float2(fmaf(acc[am][an][0], inv, b0),
                                    fmaf(acc[am][an][1], inv, b1));
            float2 v1 = make_float2(fmaf(acc[am][an][2], inv, b0),
                                    fmaf(acc[am][an][3], inv, b1));
            *(float2*)(out + (size_t)r0 * NT + c) = v0;
            *(float2*)(out + (size_t)(r0 + 8) * NT + c) = v1;
        }
    }

    // ---- fused amax EMA finalize (block 0, warp 0) ----
    if (blockIdx.x == 0 && wid == 0) {
        float mx = 0.0f, mw = 0.0f;
        for (int i = lane; i < QX_BLOCKS; i += 32) mx = fmaxf(mx, g_partX[i]);
        for (int i = lane; i < QW_BLOCKS; i += 32) mw = fmaxf(mw, g_partW[i]);
        #pragma unroll
        for (int o = 16; o > 0; o >>= 1) {
            mx = fmaxf(mx, __shfl_xor_sync(0xffffffffu, mx, o));
            mw = fmaxf(mw, __shfl_xor_sync(0xffffffffu, mw, o));
        }
        if (lane == 0) {
            out[out_size - 2] = fmaxf(fmaxf(in_amax[0] * MOMENTUM, mx), AMAX_EPS);
            out[out_size - 1] = fmaxf(fmaxf(w_amax[0] * MOMENTUM, mw), AMAX_EPS);
        }
    }
}

// ---------------- launch: 2 kernels ----------------
extern "C" void kernel_launch(void* const* d_in, const int* in_sizes, int n_in,
                              void* d_out, int out_size) {
    (void)in_sizes; (void)n_in;
    const float* x       = (const float*)d_in[0];
    const float* w       = (const float*)d_in[1];
    const float* bias    = (const float*)d_in[2];
    const float* in_amax = (const float*)d_in[3];
    const float* w_amax  = (const float*)d_in[4];
    float* out = (float*)d_out;

    quant_amax_kernel<<<Q_BLOCKS, 256>>>(x, w, in_amax, w_amax);

    cudaFuncSetAttribute(fp8_gemm_kernel,
                         cudaFuncAttributeMaxDynamicSharedMemorySize, DYN_SMEM);
    fp8_gemm_kernel<<<(MT / BM) * (NT / BN), THREADS, DYN_SMEM>>>(
        bias, in_amax, w_amax, out, out_size);
}